// round 9
// baseline (speedup 1.0000x reference)
#include <cuda_runtime.h>
#include <math_constants.h>
#include <cstdint>

#define S_LEN 1500
#define NPAIR 750
#define BATCHN 2
#define NH 8
#define DM 16
#define DFF 128
#define NROWS (BATCHN * S_LEN)          // 3000
#define XELEMS (NROWS * DM)             // 48000
#define QPB 168                         // queries per block (even)
#define YBLK 9                          // 9*168 >= 1500
#define STAG2 3008                      // floats per warp stag (2 rows + pad)
#define NSTEP2 24                       // ceil(750/32)

// Scratch (no allocations allowed)
__device__ float g_x[XELEMS];
__device__ float g_q[XELEMS];           // [B,H,S,2]
__device__ float g_k[XELEMS];
__device__ float g_v[XELEMS];
__device__ float g_ctx[XELEMS];

__device__ __forceinline__ uint32_t smem_u32(const void* p) {
    uint32_t a;
    asm("{ .reg .u64 t; cvta.to.shared.u64 t, %1; cvt.u32.u64 %0, t; }"
        : "=r"(a) : "l"(p));
    return a;
}
__device__ __forceinline__ float ex2f(float x) {
    float y;
    asm("ex2.approx.f32 %0, %1;" : "=f"(y) : "f"(x));
    return y;
}
__device__ __forceinline__ void pdl_wait() {
    asm volatile("griddepcontrol.wait;" ::: "memory");
}
__device__ __forceinline__ void pdl_trigger() {
    asm volatile("griddepcontrol.launch_dependents;" ::: "memory");
}

// ---------------------------------------------------------------------------
// embed + layer-0 qkv: 32 rows per 512-thread block
__global__ void __launch_bounds__(512) embed_kernel(
    const float* __restrict__ enc, const float* __restrict__ srcw,
    const float* __restrict__ srcb, const float* __restrict__ Wq,
    const float* __restrict__ Wk, const float* __restrict__ Wv)
{
    __shared__ float swq[256], swk[256], swv[256];
    int tid = threadIdx.x;
    if (tid < 256) { swq[tid] = Wq[tid]; swk[tid] = Wk[tid]; swv[tid] = Wv[tid]; }

    int r = tid >> 4, d = tid & 15;
    int grow = blockIdx.x * 32 + r;          // = b*1500 + s
    int lane = tid & 31, base = lane & 16;
    float xv = 0.f;
    if (grow < NROWS) {
        int s = grow % S_LEN;
        const float c = -0.57564627324851148f;   // -ln(10000)/16
        float dv = __expf((float)(d & ~1) * c);
        float ph = (float)s * dv;
        float pe = (d & 1) ? cosf(ph) : sinf(ph);
        xv = enc[grow] * srcw[d] + srcb[d] + pe;
        g_x[grow * DM + d] = xv;
    }
    __syncthreads();

    float xk[16];
#pragma unroll
    for (int k = 0; k < 16; k++) xk[k] = __shfl_sync(0xffffffffu, xv, base + k);
    if (grow < NROWS) {
        float q = 0.f, kk = 0.f, vv = 0.f;
#pragma unroll
        for (int m = 0; m < 16; m++) {
            q  = fmaf(xk[m], swq[m * 16 + d], q);
            kk = fmaf(xk[m], swk[m * 16 + d], kk);
            vv = fmaf(xk[m], swv[m * 16 + d], vv);
        }
        int b = grow / S_LEN, s = grow - b * S_LEN;
        int h = d >> 1, dk = d & 1;
        int o = ((b * NH + h) * S_LEN + s) * 2 + dk;
        g_q[o] = q; g_k[o] = kk; g_v[o] = vv;
    }
    __threadfence();
    pdl_trigger();
}

// ---------------------------------------------------------------------------
// attention: 16 warps/block (1 block/SM), 2 adjacent queries/warp/pass,
// key-pair float4 SMEM (scalar math), both rows staged contiguously and
// shipped with ONE 12000B cp.async.bulk per pair. PDL overlap with post.
__global__ void __launch_bounds__(512, 1) attn_kernel(float* __restrict__ attn_out)
{
    extern __shared__ __align__(16) float smem[];
    float4* sk2 = (float4*)smem;                 // [750] (k2j.x,k2j.y,k2j+1.x,k2j+1.y)
    float4* sv2 = (float4*)(smem + 4 * NPAIR);   // [750] same for v
    float*  stagbase = smem + 8 * NPAIR;         // [16][STAG2]

    pdl_wait();   // g_q/g_k/g_v from predecessor

    int bh = blockIdx.x;
    int tid = threadIdx.x;
    const float4* kp4 = (const float4*)(g_k + bh * S_LEN * 2);
    const float4* vp4 = (const float4*)(g_v + bh * S_LEN * 2);
    for (int i = tid; i < NPAIR; i += 512) {
        sk2[i] = kp4[i];
        sv2[i] = vp4[i];
    }
    __syncthreads();

    int warp = tid >> 5, lane = tid & 31;
    float* stag = stagbase + warp * STAG2;
    uint32_t sbuf = smem_u32(stag);
    float2* sA = (float2*)stag;                  // row A pairs
    float2* sB = (float2*)(stag + S_LEN);        // row B pairs (+6000B, 8B aligned)
    int b = bh >> 3, h = bh & 7;
    int p0 = (blockIdx.y * QPB) >> 1;
    int pend = min(blockIdx.y * QPB + QPB, S_LEN) >> 1;
    // fold 1/sqrt(dk) and log2(e) into q
    const float qscale = 0.70710678118654752f * 1.44269504088896341f;

    for (int p = p0 + warp; p < pend; p += 16) {
        int qa = 2 * p;
        float2 qva = ((const float2*)g_q)[bh * S_LEN + qa];
        float2 qvb = ((const float2*)g_q)[bh * S_LEN + qa + 1];
        qva.x *= qscale; qva.y *= qscale;
        qvb.x *= qscale; qvb.y *= qscale;

        float ea0[NSTEP2], ea1[NSTEP2], eb0[NSTEP2], eb1[NSTEP2];
        float sa = 0.f, sb = 0.f, ca0 = 0.f, ca1 = 0.f, cb0 = 0.f, cb1 = 0.f;
#pragma unroll
        for (int i = 0; i < NSTEP2; i++) {
            int j = lane + 32 * i;               // key-pair index
            if (i < NSTEP2 - 1 || j < NPAIR) {
                float4 kk = sk2[j];
                float4 vv = sv2[j];
                float A0 = ex2f(fmaf(qva.x, kk.x, qva.y * kk.y));
                float A1 = ex2f(fmaf(qva.x, kk.z, qva.y * kk.w));
                float B0 = ex2f(fmaf(qvb.x, kk.x, qvb.y * kk.y));
                float B1 = ex2f(fmaf(qvb.x, kk.z, qvb.y * kk.w));
                sa += A0 + A1; sb += B0 + B1;
                ca0 = fmaf(A0, vv.x, fmaf(A1, vv.z, ca0));
                ca1 = fmaf(A0, vv.y, fmaf(A1, vv.w, ca1));
                cb0 = fmaf(B0, vv.x, fmaf(B1, vv.z, cb0));
                cb1 = fmaf(B0, vv.y, fmaf(B1, vv.w, cb1));
                ea0[i] = A0; ea1[i] = A1; eb0[i] = B0; eb1[i] = B1;
            }
        }
#pragma unroll
        for (int o = 16; o; o >>= 1) {
            sa  += __shfl_xor_sync(0xffffffffu, sa,  o);
            sb  += __shfl_xor_sync(0xffffffffu, sb,  o);
            ca0 += __shfl_xor_sync(0xffffffffu, ca0, o);
            ca1 += __shfl_xor_sync(0xffffffffu, ca1, o);
            cb0 += __shfl_xor_sync(0xffffffffu, cb0, o);
            cb1 += __shfl_xor_sync(0xffffffffu, cb1, o);
        }
        float ra = 1.0f / sa, rb = 1.0f / sb;

        // previous pair's bulk store must have finished reading this buffer
        if (lane == 0)
            asm volatile("cp.async.bulk.wait_group.read 0;" ::: "memory");
        __syncwarp();
#pragma unroll
        for (int i = 0; i < NSTEP2; i++) {
            int j = lane + 32 * i;
            if (i < NSTEP2 - 1 || j < NPAIR) {
                sA[j] = make_float2(ea0[i] * ra, ea1[i] * ra);
                sB[j] = make_float2(eb0[i] * rb, eb1[i] * rb);
            }
        }
        __syncwarp();

        if (lane == 0) {
            asm volatile("fence.proxy.async.shared::cta;" ::: "memory");
            float* gdst = attn_out + ((size_t)bh * S_LEN + qa) * S_LEN;
            asm volatile(
                "cp.async.bulk.global.shared::cta.bulk_group [%0], [%1], %2;"
                :: "l"(gdst), "r"(sbuf), "r"((uint32_t)(2 * S_LEN * 4)) : "memory");
            asm volatile("cp.async.bulk.commit_group;" ::: "memory");

            int basea = (b * S_LEN + qa) * DM + h * 2;
            g_ctx[basea]          = ca0 * ra;
            g_ctx[basea + 1]      = ca1 * ra;
            g_ctx[basea + DM]     = cb0 * rb;
            g_ctx[basea + DM + 1] = cb1 * rb;
        }
    }
    __threadfence();
    pdl_trigger();                 // post can launch; it doesn't read attn_out
    if (lane == 0)
        asm volatile("cp.async.bulk.wait_group 0;" ::: "memory");
}

// ---------------------------------------------------------------------------
// post: x=LN(ctx@Wo+x); x=LN(relu(x@W1)@W2+x); then next-layer qkv (fused).
// Weights prefetch BEFORE pdl_wait (independent of predecessor).
__global__ void __launch_bounds__(512) post_kernel(
    const float* __restrict__ Wo, const float* __restrict__ W1,
    const float* __restrict__ W2, const float* __restrict__ Wqn,
    const float* __restrict__ Wkn, const float* __restrict__ Wvn,
    float* __restrict__ outx, int last)
{
    __shared__ float sw1[DM * DFF];
    __shared__ float sw2[DFF * DM];
    __shared__ float swo[256];
    __shared__ float swq[256], swk[256], swv[256];
    __shared__ float sh[32][DFF];

    int tid = threadIdx.x;
    if (tid < 256) swo[tid] = Wo[tid];
    for (int i = tid; i < DM * DFF; i += 512) { sw1[i] = W1[i]; sw2[i] = W2[i]; }
    if (!last && tid < 256) { swq[tid] = Wqn[tid]; swk[tid] = Wkn[tid]; swv[tid] = Wvn[tid]; }

    pdl_wait();   // g_x / g_ctx from predecessor

    int r = tid >> 4, d = tid & 15;
    int grow = blockIdx.x * 32 + r;
    int lane = tid & 31, base = lane & 16;
    bool ok = grow < NROWS;
    float xv = ok ? g_x[grow * DM + d]   : 0.f;
    float cv = ok ? g_ctx[grow * DM + d] : 0.f;
    __syncthreads();

    float s1 = xv;
#pragma unroll
    for (int k = 0; k < 16; k++) {
        float ck = __shfl_sync(0xffffffffu, cv, base + k);
        s1 = fmaf(ck, swo[k * 16 + d], s1);
    }

    float mean = s1;
#pragma unroll
    for (int o = 8; o; o >>= 1) mean += __shfl_xor_sync(0xffffffffu, mean, o);
    mean *= (1.0f / 16.0f);
    float dv = s1 - mean;
    float var = dv * dv;
#pragma unroll
    for (int o = 8; o; o >>= 1) var += __shfl_xor_sync(0xffffffffu, var, o);
    var *= (1.0f / 16.0f);
    float t = dv * rsqrtf(var + 1e-5f);

    float tk[16];
#pragma unroll
    for (int k = 0; k < 16; k++) tk[k] = __shfl_sync(0xffffffffu, t, base + k);
#pragma unroll
    for (int i = 0; i < 8; i++) {
        int j = d + 16 * i;
        float hv = 0.f;
#pragma unroll
        for (int k = 0; k < 16; k++) hv = fmaf(tk[k], sw1[k * DFF + j], hv);
        sh[r][j] = fmaxf(hv, 0.f);
    }
    __syncthreads();

    float s2 = t;
#pragma unroll
    for (int j = 0; j < DFF; j++) s2 = fmaf(sh[r][j], sw2[j * 16 + d], s2);

    float mean2 = s2;
#pragma unroll
    for (int o = 8; o; o >>= 1) mean2 += __shfl_xor_sync(0xffffffffu, mean2, o);
    mean2 *= (1.0f / 16.0f);
    float dv2 = s2 - mean2;
    float var2 = dv2 * dv2;
#pragma unroll
    for (int o = 8; o; o >>= 1) var2 += __shfl_xor_sync(0xffffffffu, var2, o);
    var2 *= (1.0f / 16.0f);
    float t2 = dv2 * rsqrtf(var2 + 1e-5f);

    if (last) {
        if (ok) outx[grow * DM + d] = t2;
        __threadfence();
        pdl_trigger();
        return;
    }
    if (ok) g_x[grow * DM + d] = t2;

    float x2k[16];
#pragma unroll
    for (int k = 0; k < 16; k++) x2k[k] = __shfl_sync(0xffffffffu, t2, base + k);
    if (ok) {
        float q = 0.f, kk = 0.f, vv = 0.f;
#pragma unroll
        for (int m = 0; m < 16; m++) {
            q  = fmaf(x2k[m], swq[m * 16 + d], q);
            kk = fmaf(x2k[m], swk[m * 16 + d], kk);
            vv = fmaf(x2k[m], swv[m * 16 + d], vv);
        }
        int b = grow / S_LEN, s = grow - b * S_LEN;
        int h = d >> 1, dk = d & 1;
        int o = ((b * NH + h) * S_LEN + s) * 2 + dk;
        g_q[o] = q; g_k[o] = kk; g_v[o] = vv;
    }
    __threadfence();
    pdl_trigger();
}

// ---------------------------------------------------------------------------
extern "C" void kernel_launch(void* const* d_in, const int* in_sizes, int n_in,
                              void* d_out, int out_size)
{
    const float* enc  = (const float*)d_in[0];
    const float* srcw = (const float*)d_in[1];
    const float* srcb = (const float*)d_in[2];
    const float* Wq   = (const float*)d_in[3];
    const float* Wk   = (const float*)d_in[4];
    const float* Wv   = (const float*)d_in[5];
    const float* Wo   = (const float*)d_in[6];
    const float* W1   = (const float*)d_in[7];
    const float* W2   = (const float*)d_in[8];
    float* out = (float*)d_out;

    const int ATTN_SMEM = (8 * NPAIR + 16 * STAG2) * (int)sizeof(float); // 216512
    static int configured = 0;
    if (!configured) {
        cudaFuncSetAttribute(attn_kernel,
                             cudaFuncAttributeMaxDynamicSharedMemorySize, ATTN_SMEM);
        configured = 1;
    }

    cudaLaunchAttribute pdlAttr[1];
    pdlAttr[0].id = cudaLaunchAttributeProgrammaticStreamSerialization;
    pdlAttr[0].val.programmaticStreamSerializationAllowed = 1;

    // embed: plain launch (first kernel in chain)
    embed_kernel<<<94, 512>>>(enc, srcw, srcb, Wq, Wk, Wv);

    for (int l = 0; l < 3; l++) {
        {
            cudaLaunchConfig_t cfg = {};
            cfg.gridDim = dim3(BATCHN * NH, YBLK);
            cfg.blockDim = dim3(512);
            cfg.dynamicSmemBytes = ATTN_SMEM;
            cfg.stream = 0;
            cfg.attrs = pdlAttr;
            cfg.numAttrs = 1;
            float* aout = out + XELEMS +
                          (size_t)l * (size_t)BATCHN * NH * S_LEN * S_LEN;
            cudaLaunchKernelEx(&cfg, attn_kernel, aout);
        }
        {
            int last = (l == 2);
            cudaLaunchConfig_t cfg = {};
            cfg.gridDim = dim3(94);
            cfg.blockDim = dim3(512);
            cfg.dynamicSmemBytes = 0;
            cfg.stream = 0;
            cfg.attrs = pdlAttr;
            cfg.numAttrs = 1;
            cudaLaunchKernelEx(&cfg, post_kernel,
                               Wo + l * 256, W1 + l * 2048, W2 + l * 2048,
                               last ? Wq : Wq + (l + 1) * 256,
                               last ? Wk : Wk + (l + 1) * 256,
                               last ? Wv : Wv + (l + 1) * 256,
                               out, last);
        }
    }
}